// round 3
// baseline (speedup 1.0000x reference)
#include <cuda_runtime.h>
#include <cuda_bf16.h>

// Problem constants
#define BATCH 256
#define TT    1024
#define INP   128
#define LAT   64
#define HID   128
#define OUTD  32

// Scratch: drive[b][t][l] (fp32), 256*1024*64 floats = 64 MB
__device__ float g_drive[(size_t)BATCH * TT * LAT];

// ---------- f32x2 helpers ----------
__device__ __forceinline__ void fma2(unsigned long long& acc,
                                     unsigned long long a,
                                     unsigned long long b) {
    asm("fma.rn.f32x2 %0, %1, %2, %0;" : "+l"(acc) : "l"(a), "l"(b));
}
__device__ __forceinline__ float psum2(unsigned long long v) {
    float lo, hi;
    asm("mov.b64 {%0,%1}, %2;" : "=f"(lo), "=f"(hi) : "l"(v));
    return lo + hi;
}
__device__ __forceinline__ void gbar(int id) {
    asm volatile("bar.sync %0, 128;" :: "r"(id) : "memory");
}

// =====================================================================
// Kernel 1: drive = input @ C^T      [B*T,128] x [64,128]^T -> [B*T,64]
// =====================================================================
__global__ void __launch_bounds__(256, 1)
drive_kernel(const float* __restrict__ inp, const float* __restrict__ Cg) {
    extern __shared__ char smem1[];
    float*  As = reinterpret_cast<float*>(smem1);                 // [128][132]
    float4* Cq = reinterpret_cast<float4*>(smem1 + 128 * 132 * 4); // [32][64]

    const int tid = threadIdx.x;
    const int m0  = blockIdx.x * 128;

    #pragma unroll
    for (int e = tid; e < 4096; e += 256) {
        int row = e >> 5;
        int c4  = e & 31;
        float4 v = reinterpret_cast<const float4*>(inp + (size_t)(m0 + row) * INP)[c4];
        *reinterpret_cast<float4*>(&As[row * 132 + c4 * 4]) = v;
    }
    #pragma unroll
    for (int idx = tid; idx < 2048; idx += 256) {
        Cq[(idx & 31) * 64 + (idx >> 5)] = reinterpret_cast<const float4*>(Cg)[idx];
    }
    __syncthreads();

    const int ctx = tid & 15;
    const int rty = tid >> 4;

    unsigned long long acc[8][4];
    #pragma unroll
    for (int r = 0; r < 8; ++r)
        #pragma unroll
        for (int c = 0; c < 4; ++c) acc[r][c] = 0ull;

    #pragma unroll 4
    for (int jq = 0; jq < 32; ++jq) {
        ulonglong2 cw[4];
        #pragma unroll
        for (int c = 0; c < 4; ++c)
            cw[c] = *reinterpret_cast<const ulonglong2*>(&Cq[jq * 64 + ctx + 16 * c]);
        #pragma unroll
        for (int r = 0; r < 8; ++r) {
            ulonglong2 av =
                *reinterpret_cast<const ulonglong2*>(&As[(rty * 8 + r) * 132 + 4 * jq]);
            #pragma unroll
            for (int c = 0; c < 4; ++c) {
                fma2(acc[r][c], av.x, cw[c].x);
                fma2(acc[r][c], av.y, cw[c].y);
            }
        }
    }

    #pragma unroll
    for (int r = 0; r < 8; ++r) {
        size_t row = (size_t)(m0 + rty * 8 + r);
        #pragma unroll
        for (int c = 0; c < 4; ++c)
            g_drive[row * LAT + ctx + 16 * c] = psum2(acc[r][c]);
    }
}

// =====================================================================
// Kernel 2: the scan. 128 blocks x 256 threads. Two independent
// 128-thread groups (one batch each) with disjoint named barriers.
// 2-D tiled matvecs: each thread = 4 rows x 16-wide chunk ->
// only 4 LDS.128 per phase; cross-chunk sums via reduce-scatter shfl.
// =====================================================================
__global__ void __launch_bounds__(256, 1)
recur_kernel(const float* __restrict__ Ag,   const float* __restrict__ W1g,
             const float* __restrict__ W2g,  const float* __restrict__ h1g,
             const float* __restrict__ h2g,  const float* __restrict__ Woutg,
             const float* __restrict__ boutg, float* __restrict__ outg) {
    __shared__ __align__(16) float zs[2][LAT];
    __shared__ __align__(16) float hid[2][HID];

    const int tid  = threadIdx.x;
    const int gid  = tid >> 7;
    const int wtid = tid & 127;
    const int bat  = blockIdx.x * 2 + gid;
    const int barid = 1 + gid;

    float* zsg  = zs[gid];
    float* hidg = hid[gid];

    // ---- phase1 mapping: rows 4*q1..+3 of W2 (128 rows), chunk c1 of z (4x16)
    const int q1 = wtid >> 2;
    const int c1 = wtid & 3;
    // ---- phase2 mapping: rows 4*g2..+3 of W1 (64 rows), chunk c2 of hidden (8x16)
    const int g2 = wtid >> 3;
    const int c2 = wtid & 7;
    const int lz = 4 * g2 + ((c2 >> 1) & 3);  // z row this lane finalizes

    // register-resident weights
    unsigned long long w2r[4][8];
    #pragma unroll
    for (int r = 0; r < 4; ++r)
        #pragma unroll
        for (int j = 0; j < 8; ++j)
            w2r[r][j] = *reinterpret_cast<const unsigned long long*>(
                &W2g[(4 * q1 + r) * LAT + 16 * c1 + 2 * j]);
    unsigned long long w1r[4][8];
    #pragma unroll
    for (int r = 0; r < 4; ++r)
        #pragma unroll
        for (int j = 0; j < 8; ++j)
            w1r[r][j] = *reinterpret_cast<const unsigned long long*>(
                &W1g[(4 * g2 + r) * HID + 16 * c2 + 2 * j]);

    const float h2h = h2g[wtid];   // phase1 output row == wtid
    const float Al  = Ag[lz];
    const float h1l = h1g[lz];

    if (wtid < LAT) zsg[wtid] = 0.0f;
    __syncthreads();

    float zcur = 0.0f;             // z[lz], register-resident
    const size_t ubase = ((size_t)bat) * TT * LAT + lz;
    float u_cur = g_drive[ubase];
    float u_nxt = g_drive[ubase + LAT];

    const unsigned FULL = 0xffffffffu;

    for (int t = 0; t < TT; ++t) {
        float u_fut = (t < TT - 2) ? g_drive[ubase + (size_t)(t + 2) * LAT] : 0.0f;

        // ================= phase 1: hidden = relu(z @ W2^T + h2) =========
        {
            ulonglong2 zv0 = *reinterpret_cast<const ulonglong2*>(&zsg[16 * c1]);
            ulonglong2 zv1 = *reinterpret_cast<const ulonglong2*>(&zsg[16 * c1 + 4]);
            ulonglong2 zv2 = *reinterpret_cast<const ulonglong2*>(&zsg[16 * c1 + 8]);
            ulonglong2 zv3 = *reinterpret_cast<const ulonglong2*>(&zsg[16 * c1 + 12]);

            float p[4];
            #pragma unroll
            for (int r = 0; r < 4; ++r) {
                unsigned long long acc = 0ull;
                fma2(acc, zv0.x, w2r[r][0]); fma2(acc, zv0.y, w2r[r][1]);
                fma2(acc, zv1.x, w2r[r][2]); fma2(acc, zv1.y, w2r[r][3]);
                fma2(acc, zv2.x, w2r[r][4]); fma2(acc, zv2.y, w2r[r][5]);
                fma2(acc, zv3.x, w2r[r][6]); fma2(acc, zv3.y, w2r[r][7]);
                p[r] = psum2(acc);
            }
            // reduce-scatter over 4 lanes (xor 2, then xor 1): lane c1 keeps row 4q1+c1
            const bool h2b = (c1 & 2);
            float s0 = h2b ? p[0] : p[2];
            float r0 = __shfl_xor_sync(FULL, s0, 2);
            float s1 = h2b ? p[1] : p[3];
            float r1 = __shfl_xor_sync(FULL, s1, 2);
            float a = (h2b ? p[2] : p[0]) + r0;
            float b = (h2b ? p[3] : p[1]) + r1;
            const bool h1b = (c1 & 1);
            float s2 = h1b ? a : b;
            float r2 = __shfl_xor_sync(FULL, s2, 1);
            float sum = (h1b ? b : a) + r2;
            hidg[wtid] = fmaxf(sum + h2h, 0.0f);
        }
        gbar(barid);

        // ================= phase 2: z' = clip(z*A + hidden @ W1^T + h1 + u)
        {
            ulonglong2 hv0 = *reinterpret_cast<const ulonglong2*>(&hidg[16 * c2]);
            ulonglong2 hv1 = *reinterpret_cast<const ulonglong2*>(&hidg[16 * c2 + 4]);
            ulonglong2 hv2 = *reinterpret_cast<const ulonglong2*>(&hidg[16 * c2 + 8]);
            ulonglong2 hv3 = *reinterpret_cast<const ulonglong2*>(&hidg[16 * c2 + 12]);

            float p[4];
            #pragma unroll
            for (int r = 0; r < 4; ++r) {
                unsigned long long acc = 0ull;
                fma2(acc, hv0.x, w1r[r][0]); fma2(acc, hv0.y, w1r[r][1]);
                fma2(acc, hv1.x, w1r[r][2]); fma2(acc, hv1.y, w1r[r][3]);
                fma2(acc, hv2.x, w1r[r][4]); fma2(acc, hv2.y, w1r[r][5]);
                fma2(acc, hv3.x, w1r[r][6]); fma2(acc, hv3.y, w1r[r][7]);
                p[r] = psum2(acc);
            }
            // reduce-scatter over 8 lanes (xor 4, xor 2, xor 1)
            const bool b4 = (c2 & 4);
            float s0 = b4 ? p[0] : p[2];
            float r0 = __shfl_xor_sync(FULL, s0, 4);
            float s1 = b4 ? p[1] : p[3];
            float r1 = __shfl_xor_sync(FULL, s1, 4);
            float a = (b4 ? p[2] : p[0]) + r0;
            float b = (b4 ? p[3] : p[1]) + r1;
            const bool b2 = (c2 & 2);
            float s2 = b2 ? a : b;
            float r2 = __shfl_xor_sync(FULL, s2, 2);
            float s = (b2 ? b : a) + r2;
            s += __shfl_xor_sync(FULL, s, 1);   // both lanes of pair get row lz

            float zn = zcur * Al + s + h1l + u_cur;
            zn = fminf(5.0f, fmaxf(-5.0f, zn));
            zcur = zn;
            if (!(c2 & 1)) zsg[lz] = zn;        // one writer per z element
        }
        u_cur = u_nxt;
        u_nxt = u_fut;
        gbar(barid);
    }

    // ---- final: out[bat][o] = zT . Wout[o] + bout[o]
    if (wtid < OUTD) {
        const int o = wtid;
        float acc = boutg[o];
        #pragma unroll
        for (int l = 0; l < LAT; ++l) acc += zsg[l] * Woutg[o * LAT + l];
        outg[(size_t)bat * OUTD + o] = acc;
    }
}

// =====================================================================
extern "C" void kernel_launch(void* const* d_in, const int* in_sizes, int n_in,
                              void* d_out, int out_size) {
    (void)in_sizes; (void)n_in; (void)out_size;
    const float* inp   = (const float*)d_in[0];
    const float* Ag    = (const float*)d_in[1];
    const float* W1g   = (const float*)d_in[2];
    const float* W2g   = (const float*)d_in[3];
    const float* h1g   = (const float*)d_in[4];
    const float* h2g   = (const float*)d_in[5];
    const float* Cg    = (const float*)d_in[6];
    const float* Woutg = (const float*)d_in[7];
    const float* boutg = (const float*)d_in[8];
    float* outg = (float*)d_out;

    const int smem1 = 128 * 132 * 4 + 32 * 64 * 16; // 100352 B
    cudaFuncSetAttribute(drive_kernel, cudaFuncAttributeMaxDynamicSharedMemorySize, smem1);

    drive_kernel<<<(BATCH * TT) / 128, 256, smem1>>>(inp, Cg);
    recur_kernel<<<BATCH / 2, 256>>>(Ag, W1g, W2g, h1g, h2g, Woutg, boutg, outg);
}

// round 4
// speedup vs baseline: 1.1056x; 1.1056x over previous
#include <cuda_runtime.h>
#include <cuda_bf16.h>

// Problem constants
#define BATCH 256
#define TT    1024
#define INP   128
#define LAT   64
#define HID   128
#define OUTD  32

// Scratch: drive[b][t][l] (fp32), 64 MB
__device__ float g_drive[(size_t)BATCH * TT * LAT];

// ---------- f32x2 helpers ----------
__device__ __forceinline__ void fma2(unsigned long long& acc,
                                     unsigned long long a,
                                     unsigned long long b) {
    asm("fma.rn.f32x2 %0, %1, %2, %0;" : "+l"(acc) : "l"(a), "l"(b));
}
__device__ __forceinline__ unsigned long long add2(unsigned long long a,
                                                   unsigned long long b) {
    unsigned long long r;
    asm("add.rn.f32x2 %0, %1, %2;" : "=l"(r) : "l"(a), "l"(b));
    return r;
}
__device__ __forceinline__ float psum2(unsigned long long v) {
    float lo, hi;
    asm("mov.b64 {%0,%1}, %2;" : "=f"(lo), "=f"(hi) : "l"(v));
    return lo + hi;
}
__device__ __forceinline__ unsigned long long pack2(float lo, float hi) {
    unsigned long long r;
    asm("mov.b64 %0, {%1,%2};" : "=l"(r) : "f"(lo), "f"(hi));
    return r;
}
__device__ __forceinline__ void unpack2(unsigned long long v, float& lo, float& hi) {
    asm("mov.b64 {%0,%1}, %2;" : "=f"(lo), "=f"(hi) : "l"(v));
}
__device__ __forceinline__ void gbar(int id) {
    asm volatile("bar.sync %0, 128;" :: "r"(id) : "memory");
}

// =====================================================================
// Kernel 1: drive = input @ C^T      [B*T,128] x [64,128]^T -> [B*T,64]
// =====================================================================
__global__ void __launch_bounds__(256, 1)
drive_kernel(const float* __restrict__ inp, const float* __restrict__ Cg) {
    extern __shared__ char smem1[];
    float*  As = reinterpret_cast<float*>(smem1);                  // [128][132]
    float4* Cq = reinterpret_cast<float4*>(smem1 + 128 * 132 * 4); // [32][64]

    const int tid = threadIdx.x;
    const int m0  = blockIdx.x * 128;

    #pragma unroll
    for (int e = tid; e < 4096; e += 256) {
        int row = e >> 5;
        int c4  = e & 31;
        float4 v = reinterpret_cast<const float4*>(inp + (size_t)(m0 + row) * INP)[c4];
        *reinterpret_cast<float4*>(&As[row * 132 + c4 * 4]) = v;
    }
    #pragma unroll
    for (int idx = tid; idx < 2048; idx += 256) {
        Cq[(idx & 31) * 64 + (idx >> 5)] = reinterpret_cast<const float4*>(Cg)[idx];
    }
    __syncthreads();

    const int ctx = tid & 15;
    const int rty = tid >> 4;

    unsigned long long acc[8][4];
    #pragma unroll
    for (int r = 0; r < 8; ++r)
        #pragma unroll
        for (int c = 0; c < 4; ++c) acc[r][c] = 0ull;

    #pragma unroll 4
    for (int jq = 0; jq < 32; ++jq) {
        ulonglong2 cw[4];
        #pragma unroll
        for (int c = 0; c < 4; ++c)
            cw[c] = *reinterpret_cast<const ulonglong2*>(&Cq[jq * 64 + ctx + 16 * c]);
        #pragma unroll
        for (int r = 0; r < 8; ++r) {
            ulonglong2 av =
                *reinterpret_cast<const ulonglong2*>(&As[(rty * 8 + r) * 132 + 4 * jq]);
            #pragma unroll
            for (int c = 0; c < 4; ++c) {
                fma2(acc[r][c], av.x, cw[c].x);
                fma2(acc[r][c], av.y, cw[c].y);
            }
        }
    }

    #pragma unroll
    for (int r = 0; r < 8; ++r) {
        size_t row = (size_t)(m0 + rty * 8 + r);
        #pragma unroll
        for (int c = 0; c < 4; ++c)
            g_drive[row * LAT + ctx + 16 * c] = psum2(acc[r][c]);
    }
}

// =====================================================================
// Kernel 2: scan. 128 blocks x 256 threads, 2 chains/block (named bars).
// Warp-local design: per-warp z copy + per-warp hidden buffer =>
// ONE block-group barrier per step (+2 syncwarp). No shfl. Registers
// hold weights, z, hidden. 4-way accumulator splits everywhere.
// =====================================================================
__global__ void __launch_bounds__(256, 1)
recur_kernel(const float* __restrict__ Ag,   const float* __restrict__ W1g,
             const float* __restrict__ W2g,  const float* __restrict__ h1g,
             const float* __restrict__ h2g,  const float* __restrict__ Woutg,
             const float* __restrict__ boutg, float* __restrict__ outg) {
    // per-chain, per-warp z copies; per-warp duplicated hidden; partials x2
    __shared__ __align__(16) float              zsg [2][4][LAT];     // 2 KB
    __shared__ __align__(16) unsigned long long hidw[2][4][32];      // 2 KB
    __shared__ __align__(16) unsigned long long zpart[2][2][4][32];  // 4 KB

    const int tid  = threadIdx.x;
    const int gid  = tid >> 7;
    const int wtid = tid & 127;
    const int w    = wtid >> 5;       // warp within chain
    const int lane = wtid & 31;
    const int bat  = blockIdx.x * 2 + gid;
    const int barid = 1 + gid;

    // phase1 weights: row wtid of W2 (32 f32x2 pairs)
    unsigned long long w2r[32];
    #pragma unroll
    for (int j = 0; j < 32; ++j)
        w2r[j] = *reinterpret_cast<const unsigned long long*>(&W2g[wtid * LAT + 2 * j]);

    // phase2 weights: w1p[r] = (W1[2*lane][32w+r], W1[2*lane+1][32w+r])
    unsigned long long w1p[32];
    #pragma unroll
    for (int r = 0; r < 32; ++r)
        w1p[r] = pack2(W1g[(2 * lane) * HID + 32 * w + r],
                       W1g[(2 * lane + 1) * HID + 32 * w + r]);

    const float h2h = h2g[wtid];
    const float a0c = Ag[2 * lane];
    const float a1c = Ag[2 * lane + 1];
    const float h10 = h1g[2 * lane];
    const float h11 = h1g[2 * lane + 1];

    // init per-warp z copies to 0
    *reinterpret_cast<float2*>(&zsg[gid][w][2 * lane]) = make_float2(0.f, 0.f);
    __syncthreads();

    float zc0 = 0.f, zc1 = 0.f;   // register-resident z[2*lane], z[2*lane+1]
    const size_t ubase = ((size_t)bat) * TT * LAT + 2 * lane;
    float2 u_cur = *reinterpret_cast<const float2*>(&g_drive[ubase]);
    float2 u_nxt = *reinterpret_cast<const float2*>(&g_drive[ubase + LAT]);

    const float* zrow = zsg[gid][w];
    const unsigned long long* hrow = hidw[gid][w];

    for (int t = 0; t < TT; ++t) {
        const int tp = (t + 2 < TT) ? (t + 2) : (TT - 1);
        float2 u_fut = *reinterpret_cast<const float2*>(&g_drive[ubase + (size_t)tp * LAT]);

        // ---- phase 1: hval = relu( z . W2[wtid] + h2 )  (warp-local z copy)
        unsigned long long a0 = 0, a1 = 0, a2 = 0, a3 = 0;
        #pragma unroll
        for (int i = 0; i < 8; ++i) {
            ulonglong2 zq0 = *reinterpret_cast<const ulonglong2*>(&zrow[8 * i]);
            ulonglong2 zq1 = *reinterpret_cast<const ulonglong2*>(&zrow[8 * i + 4]);
            fma2(a0, zq0.x, w2r[4 * i]);
            fma2(a1, zq0.y, w2r[4 * i + 1]);
            fma2(a2, zq1.x, w2r[4 * i + 2]);
            fma2(a3, zq1.y, w2r[4 * i + 3]);
        }
        float hval = fmaxf((psum2(a0) + psum2(a1)) + (psum2(a2) + psum2(a3)) + h2h, 0.f);
        hidw[gid][w][lane] = pack2(hval, hval);
        __syncwarp();

        // ---- phase 2 (k-split by warp): partial z pair over own 32 hiddens
        unsigned long long p0 = 0, p1 = 0, p2 = 0, p3 = 0;
        #pragma unroll
        for (int i = 0; i < 8; ++i) {
            ulonglong2 hq0 = *reinterpret_cast<const ulonglong2*>(&hrow[4 * i]);
            ulonglong2 hq1 = *reinterpret_cast<const ulonglong2*>(&hrow[4 * i + 2]);
            fma2(p0, hq0.x, w1p[4 * i]);
            fma2(p1, hq0.y, w1p[4 * i + 1]);
            fma2(p2, hq1.x, w1p[4 * i + 2]);
            fma2(p3, hq1.y, w1p[4 * i + 3]);
        }
        zpart[t & 1][gid][w][lane] = add2(add2(p0, p1), add2(p2, p3));
        gbar(barid);

        // ---- finalize (redundant in every warp; z stays in registers)
        unsigned long long q0 = zpart[t & 1][gid][0][lane];
        unsigned long long q1 = zpart[t & 1][gid][1][lane];
        unsigned long long q2 = zpart[t & 1][gid][2][lane];
        unsigned long long q3 = zpart[t & 1][gid][3][lane];
        float s0, s1;
        unpack2(add2(add2(q0, q1), add2(q2, q3)), s0, s1);

        float zn0 = zc0 * a0c + s0 + h10 + u_cur.x;
        float zn1 = zc1 * a1c + s1 + h11 + u_cur.y;
        zn0 = fminf(5.0f, fmaxf(-5.0f, zn0));
        zn1 = fminf(5.0f, fmaxf(-5.0f, zn1));
        zc0 = zn0; zc1 = zn1;
        *reinterpret_cast<float2*>(&zsg[gid][w][2 * lane]) = make_float2(zn0, zn1);

        u_cur = u_nxt;
        u_nxt = u_fut;
        __syncwarp();
    }

    // ---- epilogue: warp 0 of each chain (its own z copy is current)
    if (wtid < OUTD) {
        const int o = wtid;
        float acc = boutg[o];
        #pragma unroll
        for (int l = 0; l < LAT; ++l) acc += zsg[gid][0][l] * Woutg[o * LAT + l];
        outg[(size_t)bat * OUTD + o] = acc;
    }
}

// =====================================================================
extern "C" void kernel_launch(void* const* d_in, const int* in_sizes, int n_in,
                              void* d_out, int out_size) {
    (void)in_sizes; (void)n_in; (void)out_size;
    const float* inp   = (const float*)d_in[0];
    const float* Ag    = (const float*)d_in[1];
    const float* W1g   = (const float*)d_in[2];
    const float* W2g   = (const float*)d_in[3];
    const float* h1g   = (const float*)d_in[4];
    const float* h2g   = (const float*)d_in[5];
    const float* Cg    = (const float*)d_in[6];
    const float* Woutg = (const float*)d_in[7];
    const float* boutg = (const float*)d_in[8];
    float* outg = (float*)d_out;

    const int smem1 = 128 * 132 * 4 + 32 * 64 * 16; // 100352 B
    cudaFuncSetAttribute(drive_kernel, cudaFuncAttributeMaxDynamicSharedMemorySize, smem1);

    drive_kernel<<<(BATCH * TT) / 128, 256, smem1>>>(inp, Cg);
    recur_kernel<<<BATCH / 2, 256>>>(Ag, W1g, W2g, h1g, h2g, Woutg, boutg, outg);
}